// round 13
// baseline (speedup 1.0000x reference)
#include <cuda_runtime.h>
#include <cuda_fp16.h>
#include <mma.h>
#include <cstdint>

using namespace nvcuda;

#define N_NODES 10000
#define N_EDGES 640000
#define DDIM    128
#define STRIDE  192          // bucket capacity per node (deg~Poisson(64))
#define GM_ROWS 32           // gemm block tile rows
#define LDH     136          // smem leading dim (halfs), 8-half padded

// Scratch (allocation-free rule: __device__ globals).
// g_cnt: zero at module load; k_gather re-zeroes after use -> no init kernel.
__device__ int    g_cnt [N_NODES];
__device__ int    g_esrc[(size_t)N_NODES * STRIDE];   // srcs bucketed by dst
__device__ __half g_hs  [(size_t)N_NODES * DDIM];     // (x@W)*dinv[row], fp16
__device__ int    g_is64;

// ---------------------------------------------------------------------------
// K0: probe adj dtype (int64 node ids have high word 0).
__global__ void k_probe(const void* __restrict__ adj) {
    if (threadIdx.x == 0) {
        const long long* a = (const long long*)adj;
        int is64 = 1;
        for (int k = 0; k < 64; k++) {
            long long v = a[k];
            if (v < 0 || v > (long long)N_NODES) { is64 = 0; break; }
        }
        g_is64 = is64;
    }
}

// K1: bucket scatter — 2 edges per thread, paired index loads.
__global__ void k_scatter(const void* __restrict__ adj, int e) {
    int i = (blockIdx.x * blockDim.x + threadIdx.x) * 2;
    if (i >= e) return;

    int s0, s1, d0, d1;
    if (g_is64) {
        const long long* a = (const long long*)adj;
        longlong2 sp = *(const longlong2*)(a + i);
        longlong2 dp = *(const longlong2*)(a + e + i);
        s0 = (int)sp.x; s1 = (int)sp.y;
        d0 = (int)dp.x; d1 = (int)dp.y;
    } else {
        const int* a = (const int*)adj;
        int2 sp = *(const int2*)(a + i);
        int2 dp = *(const int2*)(a + e + i);
        s0 = sp.x; s1 = sp.y;
        d0 = dp.x; d1 = dp.y;
    }

    int p0 = atomicAdd(&g_cnt[d0], 1);
    g_esrc[(size_t)d0 * STRIDE + p0] = s0;
    if (i + 1 < e) {
        int p1 = atomicAdd(&g_cnt[d1], 1);
        g_esrc[(size_t)d1 * STRIDE + p1] = s1;
    }
}

// ---------------------------------------------------------------------------
// K2: hs = fp16( (x @ W) * rsqrt(deg+1) )  via wmma tensor cores.
// Block = 256 thr (8 warps), tile 32 rows x 128 cols. W -> fp16 smem once per
// block; HMMA does the math (proven R12: gemm ~4-5us).
__global__ void __launch_bounds__(256) k_gemm(const float* __restrict__ x,
                                              const float* __restrict__ W,
                                              int n) {
    __shared__ alignas(16) unsigned char sbuf[128 * LDH * 2 + GM_ROWS * LDH * 2];
    __half* Wsh = (__half*)sbuf;                        // 128 x LDH halfs
    __half* xsh = (__half*)(sbuf + 128 * LDH * 2);      // 32  x LDH halfs
    float*  osh = (float*)sbuf;                         // alias after mma

    const int t = threadIdx.x;
    const int block_row = blockIdx.x * GM_ROWS;

    {
        const float4* Wg = (const float4*)W;
        for (int i = t; i < 128 * 32; i += 256) {
            int k = i >> 5, g = i & 31;
            float4 v = Wg[i];
            __half2 h0 = __floats2half2_rn(v.x, v.y);
            __half2 h1 = __floats2half2_rn(v.z, v.w);
            *(__half2*)(Wsh + k * LDH + g * 4)     = h0;
            *(__half2*)(Wsh + k * LDH + g * 4 + 2) = h1;
        }
    }
    {
        for (int i = t; i < GM_ROWS * 32; i += 256) {
            int r = i >> 5, g = i & 31;
            int row = block_row + r;
            float4 v = (row < n) ? ((const float4*)x)[(size_t)row * 32 + g]
                                 : make_float4(0.f, 0.f, 0.f, 0.f);
            __half2 h0 = __floats2half2_rn(v.x, v.y);
            __half2 h1 = __floats2half2_rn(v.z, v.w);
            *(__half2*)(xsh + r * LDH + g * 4)     = h0;
            *(__half2*)(xsh + r * LDH + g * 4 + 2) = h1;
        }
    }
    __syncthreads();

    const int wid = t >> 5;
    const int wm  = wid >> 2;       // 0..1
    const int wn  = wid & 3;        // 0..3

    wmma::fragment<wmma::accumulator, 16, 16, 16, float> acc0, acc1;
    wmma::fill_fragment(acc0, 0.0f);
    wmma::fill_fragment(acc1, 0.0f);

#pragma unroll
    for (int ks = 0; ks < 8; ks++) {
        wmma::fragment<wmma::matrix_a, 16, 16, 16, __half, wmma::row_major> a;
        wmma::fragment<wmma::matrix_b, 16, 16, 16, __half, wmma::row_major> b0, b1;
        wmma::load_matrix_sync(a,  xsh + wm * 16 * LDH + ks * 16, LDH);
        wmma::load_matrix_sync(b0, Wsh + ks * 16 * LDH + wn * 32, LDH);
        wmma::load_matrix_sync(b1, Wsh + ks * 16 * LDH + wn * 32 + 16, LDH);
        wmma::mma_sync(acc0, a, b0, acc0);
        wmma::mma_sync(acc1, a, b1, acc1);
    }
    __syncthreads();    // all Wsh/xsh reads done before aliasing as osh

    wmma::store_matrix_sync(osh + (wm * 16) * 128 + wn * 32,      acc0, 128,
                            wmma::mem_row_major);
    wmma::store_matrix_sync(osh + (wm * 16) * 128 + wn * 32 + 16, acc1, 128,
                            wmma::mem_row_major);
    __syncthreads();

    for (int i = t; i < GM_ROWS * 32; i += 256) {
        int r = i >> 5, g = i & 31;
        int row = block_row + r;
        if (row < n) {
            float di = rsqrtf((float)(g_cnt[row] + 1));
            const float* src = osh + r * 128 + g * 4;
            __half2 h0 = __floats2half2_rn(src[0] * di, src[1] * di);
            __half2 h1 = __floats2half2_rn(src[2] * di, src[3] * di);
            uint2 v;
            v.x = *(unsigned*)&h0;
            v.y = *(unsigned*)&h1;
            *(uint2*)(g_hs + (size_t)row * DDIM + g * 4) = v;
        }
    }
}

// ---------------------------------------------------------------------------
__device__ __forceinline__ __half2 u2h(unsigned u) { return *(__half2*)&u; }

__device__ __forceinline__ void acc_add(float4& a, uint2 v) {
    float2 f0 = __half22float2(u2h(v.x));
    float2 f1 = __half22float2(u2h(v.y));
    a.x += f0.x; a.y += f0.y; a.z += f1.x; a.w += f1.y;
}

// K3: per-node gather, 1 node/warp (proven R11 best: occ 53%, issue 40%).
// 8-edge chunks: 2 uniform LDG.128 index loads, 8 MLP gathers, HADD2 tree.
// Also re-zeroes g_cnt[w] so the next graph replay starts clean (replaces
// the k_init kernel).
__global__ void k_gather(const float* __restrict__ b, float* __restrict__ out,
                         int n) {
    int w    = (blockIdx.x * blockDim.x + threadIdx.x) >> 5;
    int lane = threadIdx.x & 31;
    if (w >= n) return;

    const uint2* hs  = (const uint2*)g_hs;          // 32 uint2 per row
    const int*   row = g_esrc + (size_t)w * STRIDE; // 16B-aligned
    int deg = g_cnt[w];
    if (lane == 0) g_cnt[w] = 0;                    // reset for next replay

    float4 acc = make_float4(0.f, 0.f, 0.f, 0.f);
    acc_add(acc, hs[(size_t)w * 32 + lane]);        // self-loop term

    int kmain = deg & ~7;
    for (int k = 0; k < kmain; k += 8) {
        int4 i0 = *(const int4*)(row + k);          // uniform broadcast
        int4 i1 = *(const int4*)(row + k + 4);

        uint2 v0 = hs[(size_t)i0.x * 32 + lane];
        uint2 v1 = hs[(size_t)i0.y * 32 + lane];
        uint2 v2 = hs[(size_t)i0.z * 32 + lane];
        uint2 v3 = hs[(size_t)i0.w * 32 + lane];
        uint2 v4 = hs[(size_t)i1.x * 32 + lane];
        uint2 v5 = hs[(size_t)i1.y * 32 + lane];
        uint2 v6 = hs[(size_t)i1.z * 32 + lane];
        uint2 v7 = hs[(size_t)i1.w * 32 + lane];

        __half2 l01 = __hadd2(u2h(v0.x), u2h(v1.x));
        __half2 l23 = __hadd2(u2h(v2.x), u2h(v3.x));
        __half2 l45 = __hadd2(u2h(v4.x), u2h(v5.x));
        __half2 l67 = __hadd2(u2h(v6.x), u2h(v7.x));
        __half2 lo  = __hadd2(__hadd2(l01, l23), __hadd2(l45, l67));

        __half2 h01 = __hadd2(u2h(v0.y), u2h(v1.y));
        __half2 h23 = __hadd2(u2h(v2.y), u2h(v3.y));
        __half2 h45 = __hadd2(u2h(v4.y), u2h(v5.y));
        __half2 h67 = __hadd2(u2h(v6.y), u2h(v7.y));
        __half2 hi  = __hadd2(__hadd2(h01, h23), __hadd2(h45, h67));

        float2 fl = __half22float2(lo);
        float2 fh = __half22float2(hi);
        acc.x += fl.x; acc.y += fl.y; acc.z += fh.x; acc.w += fh.y;
    }

    for (int k = kmain; k < deg; k++) {             // tail <8, fp32 path
        int s = row[k];
        acc_add(acc, hs[(size_t)s * 32 + lane]);
    }

    float di = rsqrtf((float)(deg + 1));
    float4 bb = ((const float4*)b)[lane];
    float4 o = make_float4(bb.x + di * acc.x, bb.y + di * acc.y,
                           bb.z + di * acc.z, bb.w + di * acc.w);
    ((float4*)out)[(size_t)w * 32 + lane] = o;
}

// ---------------------------------------------------------------------------
extern "C" void kernel_launch(void* const* d_in, const int* in_sizes, int n_in,
                              void* d_out, int out_size) {
    const float* x   = (const float*)d_in[0];
    const void*  adj = (const void*)d_in[1];
    const float* W   = (const float*)d_in[2];
    const float* b   = (const float*)d_in[3];
    float*       out = (float*)d_out;

    int n = in_sizes[0] / DDIM;   // 10000
    int e = in_sizes[1] / 2;      // 640000

    k_probe  <<<1, 32>>>(adj);
    int pairs = (e + 1) / 2;
    k_scatter<<<(pairs + 255) / 256, 256>>>(adj, e);
    k_gemm   <<<(n + GM_ROWS - 1) / GM_ROWS, 256>>>(x, W, n);

    long long threads_needed = (long long)n * 32;   // one warp per node
    int blocks = (int)((threads_needed + 255) / 256);
    k_gather <<<blocks, 256>>>(b, out, n);
}

// round 14
// speedup vs baseline: 1.2676x; 1.2676x over previous
#include <cuda_runtime.h>
#include <cuda_fp16.h>
#include <mma.h>
#include <cstdint>

using namespace nvcuda;

#define N_NODES 10000
#define N_EDGES 640000
#define DDIM    128
#define STRIDE  192          // bucket capacity per node (deg~Poisson(64))
#define GM_ROWS 32           // gemm block tile rows
#define LDH     136          // smem leading dim (halfs), 8-half padded

// Scratch (allocation-free rule: __device__ globals)
__device__ int    g_cnt [N_NODES];
__device__ int    g_esrc[(size_t)N_NODES * STRIDE];   // srcs bucketed by dst
__device__ __half g_hs  [(size_t)N_NODES * DDIM];     // (x@W)*dinv[row], fp16
__device__ int    g_is64;

// ---------------------------------------------------------------------------
// K1: zero counts + probe adj dtype (int64 node ids have high word 0).
// NOTE: keep the zeroing in its own kernel. R13 moved the g_cnt reset into
// k_gather (a single STG) and the gather's MLP load batching collapsed
// (20.9us -> 35.3us, issue 40% -> 22%): a preceding global store blocks
// ptxas from batching the 8 gather LDGs. Store-free gather is load-bearing.
__global__ void k_init(const void* __restrict__ adj, int n) {
    int i = blockIdx.x * blockDim.x + threadIdx.x;
    if (i < n) g_cnt[i] = 0;
    if (i == 0) {
        const long long* a = (const long long*)adj;
        int is64 = 1;
        for (int k = 0; k < 64; k++) {
            long long v = a[k];
            if (v < 0 || v > (long long)N_NODES) { is64 = 0; break; }
        }
        g_is64 = is64;
    }
}

// K2: bucket scatter — 2 edges per thread, paired index loads.
__global__ void k_scatter(const void* __restrict__ adj, int e) {
    int i = (blockIdx.x * blockDim.x + threadIdx.x) * 2;
    if (i >= e) return;

    int s0, s1, d0, d1;
    if (g_is64) {
        const long long* a = (const long long*)adj;
        longlong2 sp = *(const longlong2*)(a + i);
        longlong2 dp = *(const longlong2*)(a + e + i);
        s0 = (int)sp.x; s1 = (int)sp.y;
        d0 = (int)dp.x; d1 = (int)dp.y;
    } else {
        const int* a = (const int*)adj;
        int2 sp = *(const int2*)(a + i);
        int2 dp = *(const int2*)(a + e + i);
        s0 = sp.x; s1 = sp.y;
        d0 = dp.x; d1 = dp.y;
    }

    int p0 = atomicAdd(&g_cnt[d0], 1);
    g_esrc[(size_t)d0 * STRIDE + p0] = s0;
    if (i + 1 < e) {
        int p1 = atomicAdd(&g_cnt[d1], 1);
        g_esrc[(size_t)d1 * STRIDE + p1] = s1;
    }
}

// ---------------------------------------------------------------------------
// K3: hs = fp16( (x @ W) * rsqrt(deg+1) )  via wmma tensor cores.
// Block = 256 thr (8 warps), tile 32 rows x 128 cols. W -> fp16 smem once per
// block; HMMA does the math (proven R12: gemm ~4-5us).
__global__ void __launch_bounds__(256) k_gemm(const float* __restrict__ x,
                                              const float* __restrict__ W,
                                              int n) {
    __shared__ alignas(16) unsigned char sbuf[128 * LDH * 2 + GM_ROWS * LDH * 2];
    __half* Wsh = (__half*)sbuf;                        // 128 x LDH halfs
    __half* xsh = (__half*)(sbuf + 128 * LDH * 2);      // 32  x LDH halfs
    float*  osh = (float*)sbuf;                         // alias after mma

    const int t = threadIdx.x;
    const int block_row = blockIdx.x * GM_ROWS;

    {
        const float4* Wg = (const float4*)W;
        for (int i = t; i < 128 * 32; i += 256) {
            int k = i >> 5, g = i & 31;
            float4 v = Wg[i];
            __half2 h0 = __floats2half2_rn(v.x, v.y);
            __half2 h1 = __floats2half2_rn(v.z, v.w);
            *(__half2*)(Wsh + k * LDH + g * 4)     = h0;
            *(__half2*)(Wsh + k * LDH + g * 4 + 2) = h1;
        }
    }
    {
        for (int i = t; i < GM_ROWS * 32; i += 256) {
            int r = i >> 5, g = i & 31;
            int row = block_row + r;
            float4 v = (row < n) ? ((const float4*)x)[(size_t)row * 32 + g]
                                 : make_float4(0.f, 0.f, 0.f, 0.f);
            __half2 h0 = __floats2half2_rn(v.x, v.y);
            __half2 h1 = __floats2half2_rn(v.z, v.w);
            *(__half2*)(xsh + r * LDH + g * 4)     = h0;
            *(__half2*)(xsh + r * LDH + g * 4 + 2) = h1;
        }
    }
    __syncthreads();

    const int wid = t >> 5;
    const int wm  = wid >> 2;       // 0..1
    const int wn  = wid & 3;        // 0..3

    wmma::fragment<wmma::accumulator, 16, 16, 16, float> acc0, acc1;
    wmma::fill_fragment(acc0, 0.0f);
    wmma::fill_fragment(acc1, 0.0f);

#pragma unroll
    for (int ks = 0; ks < 8; ks++) {
        wmma::fragment<wmma::matrix_a, 16, 16, 16, __half, wmma::row_major> a;
        wmma::fragment<wmma::matrix_b, 16, 16, 16, __half, wmma::row_major> b0, b1;
        wmma::load_matrix_sync(a,  xsh + wm * 16 * LDH + ks * 16, LDH);
        wmma::load_matrix_sync(b0, Wsh + ks * 16 * LDH + wn * 32, LDH);
        wmma::load_matrix_sync(b1, Wsh + ks * 16 * LDH + wn * 32 + 16, LDH);
        wmma::mma_sync(acc0, a, b0, acc0);
        wmma::mma_sync(acc1, a, b1, acc1);
    }
    __syncthreads();    // all Wsh/xsh reads done before aliasing as osh

    wmma::store_matrix_sync(osh + (wm * 16) * 128 + wn * 32,      acc0, 128,
                            wmma::mem_row_major);
    wmma::store_matrix_sync(osh + (wm * 16) * 128 + wn * 32 + 16, acc1, 128,
                            wmma::mem_row_major);
    __syncthreads();

    for (int i = t; i < GM_ROWS * 32; i += 256) {
        int r = i >> 5, g = i & 31;
        int row = block_row + r;
        if (row < n) {
            float di = rsqrtf((float)(g_cnt[row] + 1));
            const float* src = osh + r * 128 + g * 4;
            __half2 h0 = __floats2half2_rn(src[0] * di, src[1] * di);
            __half2 h1 = __floats2half2_rn(src[2] * di, src[3] * di);
            uint2 v;
            v.x = *(unsigned*)&h0;
            v.y = *(unsigned*)&h1;
            *(uint2*)(g_hs + (size_t)row * DDIM + g * 4) = v;
        }
    }
}

// ---------------------------------------------------------------------------
__device__ __forceinline__ __half2 u2h(unsigned u) { return *(__half2*)&u; }

__device__ __forceinline__ void acc_add(float4& a, uint2 v) {
    float2 f0 = __half22float2(u2h(v.x));
    float2 f1 = __half22float2(u2h(v.y));
    a.x += f0.x; a.y += f0.y; a.z += f1.x; a.w += f1.y;
}

// K4: per-node gather — EXACT R11 body (measured 20.9us, occ 53%, issue 40%).
// One warp per node; lane owns 4 cols. 8-edge chunks: 2 uniform LDG.128
// index loads, 8 MLP gathers, HADD2 pairwise tree, fp32 fold per chunk.
// Store-free until the final output write (see k_init note).
__global__ void k_gather(const float* __restrict__ b, float* __restrict__ out,
                         int n) {
    int w    = (blockIdx.x * blockDim.x + threadIdx.x) >> 5;
    int lane = threadIdx.x & 31;
    if (w >= n) return;

    const uint2* hs  = (const uint2*)g_hs;          // 32 uint2 per row
    const int*   row = g_esrc + (size_t)w * STRIDE; // 16B-aligned
    int deg = g_cnt[w];

    float4 acc = make_float4(0.f, 0.f, 0.f, 0.f);
    acc_add(acc, hs[(size_t)w * 32 + lane]);        // self-loop term

    int kmain = deg & ~7;
    for (int k = 0; k < kmain; k += 8) {
        int4 i0 = *(const int4*)(row + k);          // uniform broadcast
        int4 i1 = *(const int4*)(row + k + 4);

        uint2 v0 = hs[(size_t)i0.x * 32 + lane];
        uint2 v1 = hs[(size_t)i0.y * 32 + lane];
        uint2 v2 = hs[(size_t)i0.z * 32 + lane];
        uint2 v3 = hs[(size_t)i0.w * 32 + lane];
        uint2 v4 = hs[(size_t)i1.x * 32 + lane];
        uint2 v5 = hs[(size_t)i1.y * 32 + lane];
        uint2 v6 = hs[(size_t)i1.z * 32 + lane];
        uint2 v7 = hs[(size_t)i1.w * 32 + lane];

        __half2 l01 = __hadd2(u2h(v0.x), u2h(v1.x));
        __half2 l23 = __hadd2(u2h(v2.x), u2h(v3.x));
        __half2 l45 = __hadd2(u2h(v4.x), u2h(v5.x));
        __half2 l67 = __hadd2(u2h(v6.x), u2h(v7.x));
        __half2 lo  = __hadd2(__hadd2(l01, l23), __hadd2(l45, l67));

        __half2 h01 = __hadd2(u2h(v0.y), u2h(v1.y));
        __half2 h23 = __hadd2(u2h(v2.y), u2h(v3.y));
        __half2 h45 = __hadd2(u2h(v4.y), u2h(v5.y));
        __half2 h67 = __hadd2(u2h(v6.y), u2h(v7.y));
        __half2 hi  = __hadd2(__hadd2(h01, h23), __hadd2(h45, h67));

        float2 fl = __half22float2(lo);
        float2 fh = __half22float2(hi);
        acc.x += fl.x; acc.y += fl.y; acc.z += fh.x; acc.w += fh.y;
    }

    for (int k = kmain; k < deg; k++) {             // tail <8, fp32 path
        int s = row[k];
        acc_add(acc, hs[(size_t)s * 32 + lane]);
    }

    float di = rsqrtf((float)(deg + 1));
    float4 bb = ((const float4*)b)[lane];
    float4 o = make_float4(bb.x + di * acc.x, bb.y + di * acc.y,
                           bb.z + di * acc.z, bb.w + di * acc.w);
    ((float4*)out)[(size_t)w * 32 + lane] = o;
}

// ---------------------------------------------------------------------------
extern "C" void kernel_launch(void* const* d_in, const int* in_sizes, int n_in,
                              void* d_out, int out_size) {
    const float* x   = (const float*)d_in[0];
    const void*  adj = (const void*)d_in[1];
    const float* W   = (const float*)d_in[2];
    const float* b   = (const float*)d_in[3];
    float*       out = (float*)d_out;

    int n = in_sizes[0] / DDIM;   // 10000
    int e = in_sizes[1] / 2;      // 640000

    k_init   <<<(n + 255) / 256, 256>>>(adj, n);
    int pairs = (e + 1) / 2;
    k_scatter<<<(pairs + 255) / 256, 256>>>(adj, e);
    k_gemm   <<<(n + GM_ROWS - 1) / GM_ROWS, 256>>>(x, W, n);

    long long threads_needed = (long long)n * 32;   // one warp per node
    int blocks = (int)((threads_needed + 255) / 256);
    k_gather <<<blocks, 256>>>(b, out, n);
}

// round 15
// speedup vs baseline: 1.3006x; 1.0260x over previous
#include <cuda_runtime.h>
#include <cuda_fp16.h>
#include <mma.h>
#include <cstdint>

using namespace nvcuda;

#define N_NODES 10000
#define N_EDGES 640000
#define DDIM    128
#define STRIDE  192          // bucket capacity per node (deg~Poisson(64))
#define GM_ROWS 32           // gemm block tile rows
#define LDH     136          // smem leading dim (halfs), 8-half padded

// Scratch (allocation-free rule: __device__ globals)
__device__ int    g_cnt [N_NODES];
__device__ int    g_esrc[(size_t)N_NODES * STRIDE];   // srcs bucketed by dst
__device__ __half g_hs  [(size_t)N_NODES * DDIM];     // (x@W)*dinv[row], fp16
__device__ int    g_is64;

// ---------------------------------------------------------------------------
// K1: zero counts + probe adj dtype (int64 node ids have high word 0).
// NOTE: keep the zeroing OUT of k_gather. R13 put a single STG in the gather
// and its MLP load batching collapsed (20.9us -> 35.3us). Store-free gather
// is load-bearing.
__global__ void k_init(const void* __restrict__ adj, int n) {
    int i = blockIdx.x * blockDim.x + threadIdx.x;
    if (i < n) g_cnt[i] = 0;
    if (i == 0) {
        const long long* a = (const long long*)adj;
        int is64 = 1;
        for (int k = 0; k < 64; k++) {
            long long v = a[k];
            if (v < 0 || v > (long long)N_NODES) { is64 = 0; break; }
        }
        g_is64 = is64;
    }
}

// K2: bucket scatter — 2 edges per thread, paired index loads.
__global__ void k_scatter(const void* __restrict__ adj, int e) {
    int i = (blockIdx.x * blockDim.x + threadIdx.x) * 2;
    if (i >= e) return;

    int s0, s1, d0, d1;
    if (g_is64) {
        const long long* a = (const long long*)adj;
        longlong2 sp = *(const longlong2*)(a + i);
        longlong2 dp = *(const longlong2*)(a + e + i);
        s0 = (int)sp.x; s1 = (int)sp.y;
        d0 = (int)dp.x; d1 = (int)dp.y;
    } else {
        const int* a = (const int*)adj;
        int2 sp = *(const int2*)(a + i);
        int2 dp = *(const int2*)(a + e + i);
        s0 = sp.x; s1 = sp.y;
        d0 = dp.x; d1 = dp.y;
    }

    int p0 = atomicAdd(&g_cnt[d0], 1);
    g_esrc[(size_t)d0 * STRIDE + p0] = s0;
    if (i + 1 < e) {
        int p1 = atomicAdd(&g_cnt[d1], 1);
        g_esrc[(size_t)d1 * STRIDE + p1] = s1;
    }
}

// ---------------------------------------------------------------------------
// K3: hs = fp16( (x @ W) * rsqrt(deg+1) )  via wmma tensor cores.
// Block = 256 thr (8 warps), tile 32 rows x 128 cols (proven R12: ~4-5us).
__global__ void __launch_bounds__(256) k_gemm(const float* __restrict__ x,
                                              const float* __restrict__ W,
                                              int n) {
    __shared__ alignas(16) unsigned char sbuf[128 * LDH * 2 + GM_ROWS * LDH * 2];
    __half* Wsh = (__half*)sbuf;                        // 128 x LDH halfs
    __half* xsh = (__half*)(sbuf + 128 * LDH * 2);      // 32  x LDH halfs
    float*  osh = (float*)sbuf;                         // alias after mma

    const int t = threadIdx.x;
    const int block_row = blockIdx.x * GM_ROWS;

    {
        const float4* Wg = (const float4*)W;
        for (int i = t; i < 128 * 32; i += 256) {
            int k = i >> 5, g = i & 31;
            float4 v = Wg[i];
            __half2 h0 = __floats2half2_rn(v.x, v.y);
            __half2 h1 = __floats2half2_rn(v.z, v.w);
            *(__half2*)(Wsh + k * LDH + g * 4)     = h0;
            *(__half2*)(Wsh + k * LDH + g * 4 + 2) = h1;
        }
    }
    {
        for (int i = t; i < GM_ROWS * 32; i += 256) {
            int r = i >> 5, g = i & 31;
            int row = block_row + r;
            float4 v = (row < n) ? ((const float4*)x)[(size_t)row * 32 + g]
                                 : make_float4(0.f, 0.f, 0.f, 0.f);
            __half2 h0 = __floats2half2_rn(v.x, v.y);
            __half2 h1 = __floats2half2_rn(v.z, v.w);
            *(__half2*)(xsh + r * LDH + g * 4)     = h0;
            *(__half2*)(xsh + r * LDH + g * 4 + 2) = h1;
        }
    }
    __syncthreads();

    const int wid = t >> 5;
    const int wm  = wid >> 2;       // 0..1
    const int wn  = wid & 3;        // 0..3

    wmma::fragment<wmma::accumulator, 16, 16, 16, float> acc0, acc1;
    wmma::fill_fragment(acc0, 0.0f);
    wmma::fill_fragment(acc1, 0.0f);

#pragma unroll
    for (int ks = 0; ks < 8; ks++) {
        wmma::fragment<wmma::matrix_a, 16, 16, 16, __half, wmma::row_major> a;
        wmma::fragment<wmma::matrix_b, 16, 16, 16, __half, wmma::row_major> b0, b1;
        wmma::load_matrix_sync(a,  xsh + wm * 16 * LDH + ks * 16, LDH);
        wmma::load_matrix_sync(b0, Wsh + ks * 16 * LDH + wn * 32, LDH);
        wmma::load_matrix_sync(b1, Wsh + ks * 16 * LDH + wn * 32 + 16, LDH);
        wmma::mma_sync(acc0, a, b0, acc0);
        wmma::mma_sync(acc1, a, b1, acc1);
    }
    __syncthreads();    // all Wsh/xsh reads done before aliasing as osh

    wmma::store_matrix_sync(osh + (wm * 16) * 128 + wn * 32,      acc0, 128,
                            wmma::mem_row_major);
    wmma::store_matrix_sync(osh + (wm * 16) * 128 + wn * 32 + 16, acc1, 128,
                            wmma::mem_row_major);
    __syncthreads();

    for (int i = t; i < GM_ROWS * 32; i += 256) {
        int r = i >> 5, g = i & 31;
        int row = block_row + r;
        if (row < n) {
            float di = rsqrtf((float)(g_cnt[row] + 1));
            const float* src = osh + r * 128 + g * 4;
            __half2 h0 = __floats2half2_rn(src[0] * di, src[1] * di);
            __half2 h1 = __floats2half2_rn(src[2] * di, src[3] * di);
            uint2 v;
            v.x = *(unsigned*)&h0;
            v.y = *(unsigned*)&h1;
            *(uint2*)(g_hs + (size_t)row * DDIM + g * 4) = v;
        }
    }
}

// ---------------------------------------------------------------------------
__device__ __forceinline__ __half2 u2h(unsigned u) { return *(__half2*)&u; }

__device__ __forceinline__ void acc_add(float4& a, uint2 v) {
    float2 f0 = __half22float2(u2h(v.x));
    float2 f1 = __half22float2(u2h(v.y));
    a.x += f0.x; a.y += f0.y; a.z += f1.x; a.w += f1.y;
}

// 8-edge sub-batch: 8 MLP gathers + HADD2 tree + fp32 fold.
__device__ __forceinline__ void gather8(const uint2* hs, int4 i0, int4 i1,
                                        int lane, float4& acc) {
    uint2 v0 = hs[(size_t)i0.x * 32 + lane];
    uint2 v1 = hs[(size_t)i0.y * 32 + lane];
    uint2 v2 = hs[(size_t)i0.z * 32 + lane];
    uint2 v3 = hs[(size_t)i0.w * 32 + lane];
    uint2 v4 = hs[(size_t)i1.x * 32 + lane];
    uint2 v5 = hs[(size_t)i1.y * 32 + lane];
    uint2 v6 = hs[(size_t)i1.z * 32 + lane];
    uint2 v7 = hs[(size_t)i1.w * 32 + lane];

    __half2 l01 = __hadd2(u2h(v0.x), u2h(v1.x));
    __half2 l23 = __hadd2(u2h(v2.x), u2h(v3.x));
    __half2 l45 = __hadd2(u2h(v4.x), u2h(v5.x));
    __half2 l67 = __hadd2(u2h(v6.x), u2h(v7.x));
    __half2 lo  = __hadd2(__hadd2(l01, l23), __hadd2(l45, l67));

    __half2 h01 = __hadd2(u2h(v0.y), u2h(v1.y));
    __half2 h23 = __hadd2(u2h(v2.y), u2h(v3.y));
    __half2 h45 = __hadd2(u2h(v4.y), u2h(v5.y));
    __half2 h67 = __hadd2(u2h(v6.y), u2h(v7.y));
    __half2 hi  = __hadd2(__hadd2(h01, h23), __hadd2(h45, h67));

    float2 fl = __half22float2(lo);
    float2 fh = __half22float2(hi);
    acc.x += fl.x; acc.y += fl.y; acc.z += fh.x; acc.w += fh.y;
}

// K4: per-node gather, MLP-16 version. One warp per node; lane owns 4 cols.
// 16-edge chunks: 4 uniform LDG.128 index loads + 16 independent LDG.64
// gathers batched before any consume -> 2x scoreboard-wait depth vs R14's 8
// (R14: occ 55%, issue 39%, no pipe saturated = exposed-latency bound).
// Store-free until the final output write.
__global__ void k_gather(const float* __restrict__ b, float* __restrict__ out,
                         int n) {
    int w    = (blockIdx.x * blockDim.x + threadIdx.x) >> 5;
    int lane = threadIdx.x & 31;
    if (w >= n) return;

    const uint2* hs  = (const uint2*)g_hs;          // 32 uint2 per row
    const int*   row = g_esrc + (size_t)w * STRIDE; // 16B-aligned
    int deg = g_cnt[w];

    float4 acc = make_float4(0.f, 0.f, 0.f, 0.f);
    acc_add(acc, hs[(size_t)w * 32 + lane]);        // self-loop term

    int k = 0;
    int kmain16 = deg & ~15;
    for (; k < kmain16; k += 16) {                  // 16-edge chunks (MLP 16)
        int4 i0 = *(const int4*)(row + k);          // uniform broadcasts
        int4 i1 = *(const int4*)(row + k + 4);
        int4 i2 = *(const int4*)(row + k + 8);
        int4 i3 = *(const int4*)(row + k + 12);
        gather8(hs, i0, i1, lane, acc);
        gather8(hs, i2, i3, lane, acc);
    }
    if (deg & 8) {                                  // one 8-edge chunk
        int4 i0 = *(const int4*)(row + k);
        int4 i1 = *(const int4*)(row + k + 4);
        gather8(hs, i0, i1, lane, acc);
        k += 8;
    }
    for (; k < deg; k++) {                          // tail <8, fp32 path
        int s = row[k];
        acc_add(acc, hs[(size_t)s * 32 + lane]);
    }

    float di = rsqrtf((float)(deg + 1));
    float4 bb = ((const float4*)b)[lane];
    float4 o = make_float4(bb.x + di * acc.x, bb.y + di * acc.y,
                           bb.z + di * acc.z, bb.w + di * acc.w);
    ((float4*)out)[(size_t)w * 32 + lane] = o;
}

// ---------------------------------------------------------------------------
extern "C" void kernel_launch(void* const* d_in, const int* in_sizes, int n_in,
                              void* d_out, int out_size) {
    const float* x   = (const float*)d_in[0];
    const void*  adj = (const void*)d_in[1];
    const float* W   = (const float*)d_in[2];
    const float* b   = (const float*)d_in[3];
    float*       out = (float*)d_out;

    int n = in_sizes[0] / DDIM;   // 10000
    int e = in_sizes[1] / 2;      // 640000

    k_init   <<<(n + 255) / 256, 256>>>(adj, n);
    int pairs = (e + 1) / 2;
    k_scatter<<<(pairs + 255) / 256, 256>>>(adj, e);
    k_gemm   <<<(n + GM_ROWS - 1) / GM_ROWS, 256>>>(x, W, n);

    long long threads_needed = (long long)n * 32;   // one warp per node
    int blocks = (int)((threads_needed + 255) / 256);
    k_gather <<<blocks, 256>>>(b, out, n);
}

// round 16
// speedup vs baseline: 1.3425x; 1.0323x over previous
#include <cuda_runtime.h>
#include <cuda_fp16.h>
#include <mma.h>
#include <cstdint>

using namespace nvcuda;

#define N_NODES 10000
#define N_EDGES 640000
#define DDIM    128
#define STRIDE  192          // bucket capacity per node (deg~Poisson(64))
#define GM_ROWS 32           // gemm block tile rows
#define LDH     136          // smem leading dim (halfs), 8-half padded

// Scratch (allocation-free rule: __device__ globals)
__device__ int    g_cnt [N_NODES];
__device__ int    g_esrc[(size_t)N_NODES * STRIDE];   // srcs bucketed by dst
__device__ __half g_hs  [(size_t)N_NODES * DDIM];     // (x@W)*dinv[row], fp16
__device__ int    g_is64;

// ---------------------------------------------------------------------------
// K1: zero counts + probe adj dtype (int64 node ids have high word 0).
// NOTE: keep the zeroing OUT of k_gather (R13: one STG in the gather collapsed
// its MLP load batching, 20.9us -> 35.3us).
__global__ void k_init(const void* __restrict__ adj, int n) {
    int i = blockIdx.x * blockDim.x + threadIdx.x;
    if (i < n) g_cnt[i] = 0;
    if (i == 0) {
        const long long* a = (const long long*)adj;
        int is64 = 1;
        for (int k = 0; k < 64; k++) {
            long long v = a[k];
            if (v < 0 || v > (long long)N_NODES) { is64 = 0; break; }
        }
        g_is64 = is64;
    }
}

// K2: bucket scatter — 2 edges per thread, paired index loads.
// Triggers programmatic launch of k_gemm at block entry: gemm's prologue+MMA
// (independent of g_cnt/g_esrc) overlaps the scatter.
__global__ void k_scatter(const void* __restrict__ adj, int e) {
    cudaTriggerProgrammaticLaunchCompletion();

    int i = (blockIdx.x * blockDim.x + threadIdx.x) * 2;
    if (i >= e) return;

    int s0, s1, d0, d1;
    if (g_is64) {
        const long long* a = (const long long*)adj;
        longlong2 sp = *(const longlong2*)(a + i);
        longlong2 dp = *(const longlong2*)(a + e + i);
        s0 = (int)sp.x; s1 = (int)sp.y;
        d0 = (int)dp.x; d1 = (int)dp.y;
    } else {
        const int* a = (const int*)adj;
        int2 sp = *(const int2*)(a + i);
        int2 dp = *(const int2*)(a + e + i);
        s0 = sp.x; s1 = sp.y;
        d0 = dp.x; d1 = dp.y;
    }

    int p0 = atomicAdd(&g_cnt[d0], 1);
    g_esrc[(size_t)d0 * STRIDE + p0] = s0;
    if (i + 1 < e) {
        int p1 = atomicAdd(&g_cnt[d1], 1);
        g_esrc[(size_t)d1 * STRIDE + p1] = s1;
    }
}

// ---------------------------------------------------------------------------
// K3: hs = fp16( (x @ W) * rsqrt(deg+1) )  via wmma tensor cores.
// PDL-launched: everything up to the epilogue runs concurrently with
// k_scatter; cudaGridDependencySynchronize() guards the g_cnt read.
__global__ void __launch_bounds__(256) k_gemm(const float* __restrict__ x,
                                              const float* __restrict__ W,
                                              int n) {
    __shared__ alignas(16) unsigned char sbuf[128 * LDH * 2 + GM_ROWS * LDH * 2];
    __half* Wsh = (__half*)sbuf;                        // 128 x LDH halfs
    __half* xsh = (__half*)(sbuf + 128 * LDH * 2);      // 32  x LDH halfs
    float*  osh = (float*)sbuf;                         // alias after mma

    const int t = threadIdx.x;
    const int block_row = blockIdx.x * GM_ROWS;

    {
        const float4* Wg = (const float4*)W;
        for (int i = t; i < 128 * 32; i += 256) {
            int k = i >> 5, g = i & 31;
            float4 v = Wg[i];
            __half2 h0 = __floats2half2_rn(v.x, v.y);
            __half2 h1 = __floats2half2_rn(v.z, v.w);
            *(__half2*)(Wsh + k * LDH + g * 4)     = h0;
            *(__half2*)(Wsh + k * LDH + g * 4 + 2) = h1;
        }
    }
    {
        for (int i = t; i < GM_ROWS * 32; i += 256) {
            int r = i >> 5, g = i & 31;
            int row = block_row + r;
            float4 v = (row < n) ? ((const float4*)x)[(size_t)row * 32 + g]
                                 : make_float4(0.f, 0.f, 0.f, 0.f);
            __half2 h0 = __floats2half2_rn(v.x, v.y);
            __half2 h1 = __floats2half2_rn(v.z, v.w);
            *(__half2*)(xsh + r * LDH + g * 4)     = h0;
            *(__half2*)(xsh + r * LDH + g * 4 + 2) = h1;
        }
    }
    __syncthreads();

    const int wid = t >> 5;
    const int wm  = wid >> 2;       // 0..1
    const int wn  = wid & 3;        // 0..3

    wmma::fragment<wmma::accumulator, 16, 16, 16, float> acc0, acc1;
    wmma::fill_fragment(acc0, 0.0f);
    wmma::fill_fragment(acc1, 0.0f);

#pragma unroll
    for (int ks = 0; ks < 8; ks++) {
        wmma::fragment<wmma::matrix_a, 16, 16, 16, __half, wmma::row_major> a;
        wmma::fragment<wmma::matrix_b, 16, 16, 16, __half, wmma::row_major> b0, b1;
        wmma::load_matrix_sync(a,  xsh + wm * 16 * LDH + ks * 16, LDH);
        wmma::load_matrix_sync(b0, Wsh + ks * 16 * LDH + wn * 32, LDH);
        wmma::load_matrix_sync(b1, Wsh + ks * 16 * LDH + wn * 32 + 16, LDH);
        wmma::mma_sync(acc0, a, b0, acc0);
        wmma::mma_sync(acc1, a, b1, acc1);
    }
    __syncthreads();    // all Wsh/xsh reads done before aliasing as osh

    wmma::store_matrix_sync(osh + (wm * 16) * 128 + wn * 32,      acc0, 128,
                            wmma::mem_row_major);
    wmma::store_matrix_sync(osh + (wm * 16) * 128 + wn * 32 + 16, acc1, 128,
                            wmma::mem_row_major);
    __syncthreads();

    cudaGridDependencySynchronize();   // wait for k_scatter's g_cnt

    for (int i = t; i < GM_ROWS * 32; i += 256) {
        int r = i >> 5, g = i & 31;
        int row = block_row + r;
        if (row < n) {
            float di = rsqrtf((float)(g_cnt[row] + 1));
            const float* src = osh + r * 128 + g * 4;
            __half2 h0 = __floats2half2_rn(src[0] * di, src[1] * di);
            __half2 h1 = __floats2half2_rn(src[2] * di, src[3] * di);
            uint2 v;
            v.x = *(unsigned*)&h0;
            v.y = *(unsigned*)&h1;
            *(uint2*)(g_hs + (size_t)row * DDIM + g * 4) = v;
        }
    }
}

// ---------------------------------------------------------------------------
__device__ __forceinline__ __half2 u2h(unsigned u) { return *(__half2*)&u; }

__device__ __forceinline__ void acc_add(float4& a, uint2 v) {
    float2 f0 = __half22float2(u2h(v.x));
    float2 f1 = __half22float2(u2h(v.y));
    a.x += f0.x; a.y += f0.y; a.z += f1.x; a.w += f1.y;
}

// 8-edge sub-batch: 8 MLP gathers + HADD2 tree + fp32 fold.
__device__ __forceinline__ void gather8(const uint2* hs, int4 i0, int4 i1,
                                        int lane, float4& acc) {
    uint2 v0 = hs[(size_t)i0.x * 32 + lane];
    uint2 v1 = hs[(size_t)i0.y * 32 + lane];
    uint2 v2 = hs[(size_t)i0.z * 32 + lane];
    uint2 v3 = hs[(size_t)i0.w * 32 + lane];
    uint2 v4 = hs[(size_t)i1.x * 32 + lane];
    uint2 v5 = hs[(size_t)i1.y * 32 + lane];
    uint2 v6 = hs[(size_t)i1.z * 32 + lane];
    uint2 v7 = hs[(size_t)i1.w * 32 + lane];

    __half2 l01 = __hadd2(u2h(v0.x), u2h(v1.x));
    __half2 l23 = __hadd2(u2h(v2.x), u2h(v3.x));
    __half2 l45 = __hadd2(u2h(v4.x), u2h(v5.x));
    __half2 l67 = __hadd2(u2h(v6.x), u2h(v7.x));
    __half2 lo  = __hadd2(__hadd2(l01, l23), __hadd2(l45, l67));

    __half2 h01 = __hadd2(u2h(v0.y), u2h(v1.y));
    __half2 h23 = __hadd2(u2h(v2.y), u2h(v3.y));
    __half2 h45 = __hadd2(u2h(v4.y), u2h(v5.y));
    __half2 h67 = __hadd2(u2h(v6.y), u2h(v7.y));
    __half2 hi  = __hadd2(__hadd2(h01, h23), __hadd2(h45, h67));

    float2 fl = __half22float2(lo);
    float2 fh = __half22float2(hi);
    acc.x += fl.x; acc.y += fl.y; acc.z += fh.x; acc.w += fh.y;
}

// K4: per-node gather, MLP-16 (proven R15: 19.6us, occ 77%, issue 48%).
// PDL-launched: gridDepSync at top (needs cnt/esrc/hs; gemm completion
// transitively implies scatter completion). Store-free until output write.
__global__ void k_gather(const float* __restrict__ b, float* __restrict__ out,
                         int n) {
    cudaGridDependencySynchronize();

    int w    = (blockIdx.x * blockDim.x + threadIdx.x) >> 5;
    int lane = threadIdx.x & 31;
    if (w >= n) return;

    const uint2* hs  = (const uint2*)g_hs;          // 32 uint2 per row
    const int*   row = g_esrc + (size_t)w * STRIDE; // 16B-aligned
    int deg = g_cnt[w];

    float4 acc = make_float4(0.f, 0.f, 0.f, 0.f);
    acc_add(acc, hs[(size_t)w * 32 + lane]);        // self-loop term

    int k = 0;
    int kmain16 = deg & ~15;
    for (; k < kmain16; k += 16) {                  // 16-edge chunks (MLP 16)
        int4 i0 = *(const int4*)(row + k);          // uniform broadcasts
        int4 i1 = *(const int4*)(row + k + 4);
        int4 i2 = *(const int4*)(row + k + 8);
        int4 i3 = *(const int4*)(row + k + 12);
        gather8(hs, i0, i1, lane, acc);
        gather8(hs, i2, i3, lane, acc);
    }
    if (deg & 8) {                                  // one 8-edge chunk
        int4 i0 = *(const int4*)(row + k);
        int4 i1 = *(const int4*)(row + k + 4);
        gather8(hs, i0, i1, lane, acc);
        k += 8;
    }
    for (; k < deg; k++) {                          // tail <8, fp32 path
        int s = row[k];
        acc_add(acc, hs[(size_t)s * 32 + lane]);
    }

    float di = rsqrtf((float)(deg + 1));
    float4 bb = ((const float4*)b)[lane];
    float4 o = make_float4(bb.x + di * acc.x, bb.y + di * acc.y,
                           bb.z + di * acc.z, bb.w + di * acc.w);
    ((float4*)out)[(size_t)w * 32 + lane] = o;
}

// ---------------------------------------------------------------------------
static inline void launch_pdl(void* fn, dim3 grid, dim3 block,
                              void** args) {
    cudaLaunchConfig_t cfg = {};
    cfg.gridDim  = grid;
    cfg.blockDim = block;
    cudaLaunchAttribute attr[1];
    attr[0].id = cudaLaunchAttributeProgrammaticStreamSerialization;
    attr[0].val.programmaticStreamSerializationAllowed = 1;
    cfg.attrs    = attr;
    cfg.numAttrs = 1;
    cudaLaunchKernelExC(&cfg, fn, args);
}

extern "C" void kernel_launch(void* const* d_in, const int* in_sizes, int n_in,
                              void* d_out, int out_size) {
    const float* x   = (const float*)d_in[0];
    const void*  adj = (const void*)d_in[1];
    const float* W   = (const float*)d_in[2];
    const float* b   = (const float*)d_in[3];
    float*       out = (float*)d_out;

    int n = in_sizes[0] / DDIM;   // 10000
    int e = in_sizes[1] / 2;      // 640000

    k_init   <<<(n + 255) / 256, 256>>>(adj, n);

    int pairs = (e + 1) / 2;
    k_scatter<<<(pairs + 255) / 256, 256>>>(adj, e);

    // gemm: PDL over scatter (prologue+MMA overlap; epilogue gated by
    // gridDepSync inside the kernel)
    {
        dim3 grid((n + GM_ROWS - 1) / GM_ROWS), block(256);
        void* args[] = { (void*)&x, (void*)&W, (void*)&n };
        launch_pdl((void*)k_gemm, grid, block, args);
    }

    // gather: PDL over gemm (launch-latency hiding; gridDepSync at top)
    {
        long long threads_needed = (long long)n * 32;   // one warp per node
        dim3 grid((unsigned)((threads_needed + 255) / 256)), block(256);
        void* args[] = { (void*)&b, (void*)&out, (void*)&n };
        launch_pdl((void*)k_gather, grid, block, args);
    }
}

// round 17
// speedup vs baseline: 1.3635x; 1.0156x over previous
#include <cuda_runtime.h>
#include <cuda_fp16.h>
#include <mma.h>
#include <cstdint>

using namespace nvcuda;

#define N_NODES 10000
#define N_EDGES 640000
#define DDIM    128
#define STRIDE  192          // bucket capacity per node (deg~Poisson(64))
#define GM_ROWS 32           // gemm block tile rows
#define LDH     136          // smem leading dim (halfs), 8-half padded

// Scratch (allocation-free rule: __device__ globals)
__device__ int    g_cnt [N_NODES];
__device__ int    g_esrc[(size_t)N_NODES * STRIDE];   // srcs bucketed by dst
__device__ __half g_hs  [(size_t)N_NODES * DDIM];     // (x@W)*dinv[row], fp16

// adj dtype: int32, proven in R2 — a kernel reading adj as int64 IMA'd
// (would have passed, not crashed, on a real int64 buffer). No probe needed.

// ---------------------------------------------------------------------------
// K1: zero counts. Keep zeroing OUT of k_gather (R13: one STG in the gather
// collapsed its MLP load batching, 20.9us -> 35.3us).
__global__ void k_init(int n) {
    int i = blockIdx.x * blockDim.x + threadIdx.x;
    if (i < n) g_cnt[i] = 0;
}

// K2: bucket scatter — 4 edges/thread, int4 index loads, 4 independent
// atomic->store chains (MLP 4). PDL: loads adj BEFORE gridDepSync (they
// don't depend on k_init), atomics after. Triggers k_gemm at entry.
__global__ void k_scatter(const int* __restrict__ adj, int e) {
    cudaTriggerProgrammaticLaunchCompletion();

    int i = (blockIdx.x * blockDim.x + threadIdx.x) * 4;
    if (i >= e) return;

    int4 s4, d4;
    if (i + 3 < e) {
        s4 = *(const int4*)(adj + i);           // row 0 = src
        d4 = *(const int4*)(adj + e + i);       // row 1 = dst
    } else {
        s4.x = adj[i];     d4.x = adj[e + i];
        s4.y = s4.z = s4.w = 0; d4.y = d4.z = d4.w = 0;
    }

    cudaGridDependencySynchronize();            // wait for g_cnt zeroing

    int p0 = atomicAdd(&g_cnt[d4.x], 1);
    g_esrc[(size_t)d4.x * STRIDE + p0] = s4.x;
    if (i + 1 < e) {
        int p1 = atomicAdd(&g_cnt[d4.y], 1);
        g_esrc[(size_t)d4.y * STRIDE + p1] = s4.y;
    }
    if (i + 2 < e) {
        int p2 = atomicAdd(&g_cnt[d4.z], 1);
        g_esrc[(size_t)d4.z * STRIDE + p2] = s4.z;
    }
    if (i + 3 < e) {
        int p3 = atomicAdd(&g_cnt[d4.w], 1);
        g_esrc[(size_t)d4.w * STRIDE + p3] = s4.w;
    }
}

// ---------------------------------------------------------------------------
// K3: hs = fp16( (x @ W) * rsqrt(deg+1) )  via wmma tensor cores.
// PDL-launched: prologue+MMA run concurrently with k_scatter;
// gridDepSync guards only the g_cnt-reading epilogue.
__global__ void __launch_bounds__(256) k_gemm(const float* __restrict__ x,
                                              const float* __restrict__ W,
                                              int n) {
    __shared__ alignas(16) unsigned char sbuf[128 * LDH * 2 + GM_ROWS * LDH * 2];
    __half* Wsh = (__half*)sbuf;                        // 128 x LDH halfs
    __half* xsh = (__half*)(sbuf + 128 * LDH * 2);      // 32  x LDH halfs
    float*  osh = (float*)sbuf;                         // alias after mma

    const int t = threadIdx.x;
    const int block_row = blockIdx.x * GM_ROWS;

    {
        const float4* Wg = (const float4*)W;
        for (int i = t; i < 128 * 32; i += 256) {
            int k = i >> 5, g = i & 31;
            float4 v = Wg[i];
            __half2 h0 = __floats2half2_rn(v.x, v.y);
            __half2 h1 = __floats2half2_rn(v.z, v.w);
            *(__half2*)(Wsh + k * LDH + g * 4)     = h0;
            *(__half2*)(Wsh + k * LDH + g * 4 + 2) = h1;
        }
    }
    {
        for (int i = t; i < GM_ROWS * 32; i += 256) {
            int r = i >> 5, g = i & 31;
            int row = block_row + r;
            float4 v = (row < n) ? ((const float4*)x)[(size_t)row * 32 + g]
                                 : make_float4(0.f, 0.f, 0.f, 0.f);
            __half2 h0 = __floats2half2_rn(v.x, v.y);
            __half2 h1 = __floats2half2_rn(v.z, v.w);
            *(__half2*)(xsh + r * LDH + g * 4)     = h0;
            *(__half2*)(xsh + r * LDH + g * 4 + 2) = h1;
        }
    }
    __syncthreads();

    const int wid = t >> 5;
    const int wm  = wid >> 2;       // 0..1
    const int wn  = wid & 3;        // 0..3

    wmma::fragment<wmma::accumulator, 16, 16, 16, float> acc0, acc1;
    wmma::fill_fragment(acc0, 0.0f);
    wmma::fill_fragment(acc1, 0.0f);

#pragma unroll
    for (int ks = 0; ks < 8; ks++) {
        wmma::fragment<wmma::matrix_a, 16, 16, 16, __half, wmma::row_major> a;
        wmma::fragment<wmma::matrix_b, 16, 16, 16, __half, wmma::row_major> b0, b1;
        wmma::load_matrix_sync(a,  xsh + wm * 16 * LDH + ks * 16, LDH);
        wmma::load_matrix_sync(b0, Wsh + ks * 16 * LDH + wn * 32, LDH);
        wmma::load_matrix_sync(b1, Wsh + ks * 16 * LDH + wn * 32 + 16, LDH);
        wmma::mma_sync(acc0, a, b0, acc0);
        wmma::mma_sync(acc1, a, b1, acc1);
    }
    __syncthreads();    // all Wsh/xsh reads done before aliasing as osh

    wmma::store_matrix_sync(osh + (wm * 16) * 128 + wn * 32,      acc0, 128,
                            wmma::mem_row_major);
    wmma::store_matrix_sync(osh + (wm * 16) * 128 + wn * 32 + 16, acc1, 128,
                            wmma::mem_row_major);
    __syncthreads();

    cudaGridDependencySynchronize();   // wait for k_scatter's g_cnt

    for (int i = t; i < GM_ROWS * 32; i += 256) {
        int r = i >> 5, g = i & 31;
        int row = block_row + r;
        if (row < n) {
            float di = rsqrtf((float)(g_cnt[row] + 1));
            const float* src = osh + r * 128 + g * 4;
            __half2 h0 = __floats2half2_rn(src[0] * di, src[1] * di);
            __half2 h1 = __floats2half2_rn(src[2] * di, src[3] * di);
            uint2 v;
            v.x = *(unsigned*)&h0;
            v.y = *(unsigned*)&h1;
            *(uint2*)(g_hs + (size_t)row * DDIM + g * 4) = v;
        }
    }
}

// ---------------------------------------------------------------------------
__device__ __forceinline__ __half2 u2h(unsigned u) { return *(__half2*)&u; }

__device__ __forceinline__ void acc_add(float4& a, uint2 v) {
    float2 f0 = __half22float2(u2h(v.x));
    float2 f1 = __half22float2(u2h(v.y));
    a.x += f0.x; a.y += f0.y; a.z += f1.x; a.w += f1.y;
}

// 8-edge sub-batch: 8 MLP gathers + HADD2 tree + fp32 fold.
__device__ __forceinline__ void gather8(const uint2* hs, int4 i0, int4 i1,
                                        int lane, float4& acc) {
    uint2 v0 = hs[(size_t)i0.x * 32 + lane];
    uint2 v1 = hs[(size_t)i0.y * 32 + lane];
    uint2 v2 = hs[(size_t)i0.z * 32 + lane];
    uint2 v3 = hs[(size_t)i0.w * 32 + lane];
    uint2 v4 = hs[(size_t)i1.x * 32 + lane];
    uint2 v5 = hs[(size_t)i1.y * 32 + lane];
    uint2 v6 = hs[(size_t)i1.z * 32 + lane];
    uint2 v7 = hs[(size_t)i1.w * 32 + lane];

    __half2 l01 = __hadd2(u2h(v0.x), u2h(v1.x));
    __half2 l23 = __hadd2(u2h(v2.x), u2h(v3.x));
    __half2 l45 = __hadd2(u2h(v4.x), u2h(v5.x));
    __half2 l67 = __hadd2(u2h(v6.x), u2h(v7.x));
    __half2 lo  = __hadd2(__hadd2(l01, l23), __hadd2(l45, l67));

    __half2 h01 = __hadd2(u2h(v0.y), u2h(v1.y));
    __half2 h23 = __hadd2(u2h(v2.y), u2h(v3.y));
    __half2 h45 = __hadd2(u2h(v4.y), u2h(v5.y));
    __half2 h67 = __hadd2(u2h(v6.y), u2h(v7.y));
    __half2 hi  = __hadd2(__hadd2(h01, h23), __hadd2(h45, h67));

    float2 fl = __half22float2(lo);
    float2 fh = __half22float2(hi);
    acc.x += fl.x; acc.y += fl.y; acc.z += fh.x; acc.w += fh.y;
}

// K4: per-node gather, MLP-16 (proven R15/16: ~20us, occ 75%, issue 48%).
// PDL-launched: gridDepSync at top. Store-free until output write.
__global__ void k_gather(const float* __restrict__ b, float* __restrict__ out,
                         int n) {
    cudaGridDependencySynchronize();

    int w    = (blockIdx.x * blockDim.x + threadIdx.x) >> 5;
    int lane = threadIdx.x & 31;
    if (w >= n) return;

    const uint2* hs  = (const uint2*)g_hs;          // 32 uint2 per row
    const int*   row = g_esrc + (size_t)w * STRIDE; // 16B-aligned
    int deg = g_cnt[w];

    float4 acc = make_float4(0.f, 0.f, 0.f, 0.f);
    acc_add(acc, hs[(size_t)w * 32 + lane]);        // self-loop term

    int k = 0;
    int kmain16 = deg & ~15;
    for (; k < kmain16; k += 16) {                  // 16-edge chunks (MLP 16)
        int4 i0 = *(const int4*)(row + k);          // uniform broadcasts
        int4 i1 = *(const int4*)(row + k + 4);
        int4 i2 = *(const int4*)(row + k + 8);
        int4 i3 = *(const int4*)(row + k + 12);
        gather8(hs, i0, i1, lane, acc);
        gather8(hs, i2, i3, lane, acc);
    }
    if (deg & 8) {                                  // one 8-edge chunk
        int4 i0 = *(const int4*)(row + k);
        int4 i1 = *(const int4*)(row + k + 4);
        gather8(hs, i0, i1, lane, acc);
        k += 8;
    }
    for (; k < deg; k++) {                          // tail <8, fp32 path
        int s = row[k];
        acc_add(acc, hs[(size_t)s * 32 + lane]);
    }

    float di = rsqrtf((float)(deg + 1));
    float4 bb = ((const float4*)b)[lane];
    float4 o = make_float4(bb.x + di * acc.x, bb.y + di * acc.y,
                           bb.z + di * acc.z, bb.w + di * acc.w);
    ((float4*)out)[(size_t)w * 32 + lane] = o;
}

// ---------------------------------------------------------------------------
static inline void launch_pdl(void* fn, dim3 grid, dim3 block,
                              void** args) {
    cudaLaunchConfig_t cfg = {};
    cfg.gridDim  = grid;
    cfg.blockDim = block;
    cudaLaunchAttribute attr[1];
    attr[0].id = cudaLaunchAttributeProgrammaticStreamSerialization;
    attr[0].val.programmaticStreamSerializationAllowed = 1;
    cfg.attrs    = attr;
    cfg.numAttrs = 1;
    cudaLaunchKernelExC(&cfg, fn, args);
}

extern "C" void kernel_launch(void* const* d_in, const int* in_sizes, int n_in,
                              void* d_out, int out_size) {
    const float* x   = (const float*)d_in[0];
    const int*   adj = (const int*)d_in[1];
    const float* W   = (const float*)d_in[2];
    const float* b   = (const float*)d_in[3];
    float*       out = (float*)d_out;

    int n = in_sizes[0] / DDIM;   // 10000
    int e = in_sizes[1] / 2;      // 640000

    k_init<<<(n + 255) / 256, 256>>>(n);

    // scatter: PDL over init (index loads overlap the memset; atomics gated
    // by gridDepSync inside the kernel)
    {
        int quads = (e + 3) / 4;
        dim3 grid((quads + 255) / 256), block(256);
        void* args[] = { (void*)&adj, (void*)&e };
        launch_pdl((void*)k_scatter, grid, block, args);
    }

    // gemm: PDL over scatter (prologue+MMA overlap; epilogue gated)
    {
        dim3 grid((n + GM_ROWS - 1) / GM_ROWS), block(256);
        void* args[] = { (void*)&x, (void*)&W, (void*)&n };
        launch_pdl((void*)k_gemm, grid, block, args);
    }

    // gather: PDL over gemm (launch-latency hiding; gridDepSync at top)
    {
        long long threads_needed = (long long)n * 32;   // one warp per node
        dim3 grid((unsigned)((threads_needed + 255) / 256)), block(256);
        void* args[] = { (void*)&b, (void*)&out, (void*)&n };
        launch_pdl((void*)k_gather, grid, block, args);
    }
}